// round 6
// baseline (speedup 1.0000x reference)
#include <cuda_runtime.h>
#include <cuda_bf16.h>

// QuantumFeatureMap closed form: t_q = cos(1.57*x_q), row outputs:
//   [t1t2t3, t0t1, t0t1t2, t0t1t2t3, t0t2t3, t0t3, t0, t2, t2t3, t3]
//
// R5 -> R6:
//   - __launch_bounds__(256, 8): cap regs at 32 -> 8 resident CTAs/SM (64 warps)
//   - grid = 148*8 = 1184 (one full co-resident wave), grid-stride over tiles
//   - keep warp-local smem staging + depth-2 pipelined loads + coalesced STG.128

#define QFM_ALPHA 1.57f
#define QFM_BLOCK 256
#define QFM_SMS   148
#define QFM_CTAS_PER_SM 8

__global__ void __launch_bounds__(QFM_BLOCK, QFM_CTAS_PER_SM)
qfm_kernel(const float4* __restrict__ x, float4* __restrict__ out, int n_tiles)
{
    __shared__ __align__(16) float s[QFM_BLOCK * 10];      // 10240 B

    const int tid  = threadIdx.x;
    const int warp = tid >> 5;
    const int lane = tid & 31;

    float*  ws  = s + warp * 320;            // this warp's 32 rows * 10 floats
    float4* wsv = (float4*)ws;               // 80 float4
    float2* wsp = (float2*)(ws + lane * 10); // this lane's row (40B, 8B aligned)

    const int stride = gridDim.x;

    int tile = blockIdx.x;
    if (tile >= n_tiles) return;

    // Pipeline prologue: first tile's load in flight.
    float4 v = x[(size_t)tile * QFM_BLOCK + tid];

    for (; tile < n_tiles; tile += stride) {
        // Issue next tile's load before consuming this one.
        const int next = tile + stride;
        float4 vn;
        if (next < n_tiles)
            vn = x[(size_t)next * QFM_BLOCK + tid];

        float t0 = __cosf(QFM_ALPHA * v.x);
        float t1 = __cosf(QFM_ALPHA * v.y);
        float t2 = __cosf(QFM_ALPHA * v.z);
        float t3 = __cosf(QFM_ALPHA * v.w);

        float t01 = t0 * t1;
        float t23 = t2 * t3;

        wsp[0] = make_float2(t1 * t23, t01);        // out0, out1
        wsp[1] = make_float2(t01 * t2, t01 * t23);  // out2, out3
        wsp[2] = make_float2(t0 * t23, t0 * t3);    // out4, out5
        wsp[3] = make_float2(t0, t2);               // out6, out7
        wsp[4] = make_float2(t23, t3);              // out8, out9

        __syncwarp();

        // Warp's output span: 32 rows * 40B = 1280B contiguous = 80 float4.
        // Fully coalesced STG.128.
        float4* o = out + (size_t)tile * 640 + warp * 80;
        o[lane]      = wsv[lane];
        o[lane + 32] = wsv[lane + 32];
        if (lane < 16)
            o[lane + 64] = wsv[lane + 64];

        __syncwarp();   // protect smem reuse next iteration
        v = vn;
    }
}

extern "C" void kernel_launch(void* const* d_in, const int* in_sizes, int n_in,
                              void* d_out, int out_size)
{
    const float4* x = (const float4*)d_in[0];
    float4* out = (float4*)d_out;

    const int n_rows  = in_sizes[0] / 4;             // 1048576
    const int n_tiles = n_rows / QFM_BLOCK;          // 4096
    const int grid    = QFM_SMS * QFM_CTAS_PER_SM;   // 1184

    qfm_kernel<<<grid, QFM_BLOCK>>>(x, out, n_tiles);
}

// round 7
// speedup vs baseline: 1.6066x; 1.6066x over previous
#include <cuda_runtime.h>
#include <cuda_bf16.h>
#include <cstdint>

// QuantumFeatureMap closed form: t_q = cos(1.57*x_q), row outputs:
//   [t1t2t3, t0t1, t0t1t2, t0t1t2t3, t0t2t3, t0t3, t0, t2, t2t3, t3]
//
// R6 -> R7: R5 skeleton (1024 CTAs x 4 statically-unrolled tiles, warp-local
// staging, coalesced STG.128) but input loads become cp.async.cg 16B/thread,
// ALL FOUR issued up front (4 commit groups) into a smem ring. Zero register
// cost for loads -> deep MLP without hurting occupancy. Each thread consumes
// only its own cp.async bytes, so cp.async.wait_group alone orders the input.

#define QFM_ALPHA 1.57f
#define QFM_BLOCK 256
#define QFM_ITERS 4

template <int N>
__device__ __forceinline__ void cp_wait_group() {
    asm volatile("cp.async.wait_group %0;\n" :: "n"(N) : "memory");
}

__global__ void __launch_bounds__(QFM_BLOCK)
qfm_kernel(const float4* __restrict__ x, float4* __restrict__ out)
{
    __shared__ __align__(16) float4 ins[QFM_ITERS][QFM_BLOCK];  // 16 KB input ring
    __shared__ __align__(16) float  st[QFM_BLOCK * 10];         // 10 KB store staging

    const int tid  = threadIdx.x;
    const int warp = tid >> 5;
    const int lane = tid & 31;
    const int tile0 = blockIdx.x * QFM_ITERS;

    // Front-batch all tile loads: 4 x 16B cp.async per thread, one group each.
    #pragma unroll
    for (int it = 0; it < QFM_ITERS; ++it) {
        uint32_t dst = (uint32_t)__cvta_generic_to_shared(&ins[it][tid]);
        const float4* src = x + (size_t)(tile0 + it) * QFM_BLOCK + tid;
        asm volatile("cp.async.cg.shared.global [%0], [%1], 16;\n"
                     :: "r"(dst), "l"(src) : "memory");
        asm volatile("cp.async.commit_group;\n" ::: "memory");
    }

    float*  ws  = st + warp * 320;            // warp's 32 rows * 10 floats
    float4* wsv = (float4*)ws;                // 80 float4
    float2* wsp = (float2*)(ws + lane * 10);  // this lane's row (40B)

    #pragma unroll
    for (int it = 0; it < QFM_ITERS; ++it) {
        // Wait until this tile's group has landed (later groups may stay in flight).
        if      (it == 0) cp_wait_group<QFM_ITERS - 1>();
        else if (it == 1) cp_wait_group<QFM_ITERS - 2>();
        else if (it == 2) cp_wait_group<QFM_ITERS - 3>();
        else              cp_wait_group<0>();

        float4 v = ins[it][tid];              // own bytes -> no barrier needed

        float t0 = __cosf(QFM_ALPHA * v.x);
        float t1 = __cosf(QFM_ALPHA * v.y);
        float t2 = __cosf(QFM_ALPHA * v.z);
        float t3 = __cosf(QFM_ALPHA * v.w);

        float t01 = t0 * t1;
        float t23 = t2 * t3;

        wsp[0] = make_float2(t1 * t23, t01);        // out0, out1
        wsp[1] = make_float2(t01 * t2, t01 * t23);  // out2, out3
        wsp[2] = make_float2(t0 * t23, t0 * t3);    // out4, out5
        wsp[3] = make_float2(t0, t2);               // out6, out7
        wsp[4] = make_float2(t23, t3);              // out8, out9

        __syncwarp();

        // Warp's output span: 32 rows * 40B = 1280B contiguous = 80 float4.
        float4* o = out + (size_t)(tile0 + it) * 640 + warp * 80;
        o[lane]      = wsv[lane];
        o[lane + 32] = wsv[lane + 32];
        if (lane < 16)
            o[lane + 64] = wsv[lane + 64];

        __syncwarp();   // protect staging reuse next iteration
    }
}

extern "C" void kernel_launch(void* const* d_in, const int* in_sizes, int n_in,
                              void* d_out, int out_size)
{
    const float4* x = (const float4*)d_in[0];
    float4* out = (float4*)d_out;

    const int n_rows = in_sizes[0] / 4;                   // 1048576
    const int grid = n_rows / (QFM_BLOCK * QFM_ITERS);    // 1024 CTAs

    qfm_kernel<<<grid, QFM_BLOCK>>>(x, out);
}